// round 11
// baseline (speedup 1.0000x reference)
#include <cuda_runtime.h>
#include <cuda_bf16.h>
#include <cstdint>

#define NB 64
#define NE 64
#define NC 64
#define NO 20

// ---------------- device scratch (no allocs allowed) ----------------
// activations stored as split bf16 planes (hi + lo), written by producing kernel
__device__ __nv_bfloat16 g_h1h[(size_t)NB*NE*196*NC], g_h1l[(size_t)NB*NE*196*NC];
__device__ __nv_bfloat16 g_h2h[(size_t)NB*NE*49*NC],  g_h2l[(size_t)NB*NE*49*NC];
__device__ __nv_bfloat16 g_h3h[(size_t)NB*NE*16*NC],  g_h3l[(size_t)NB*NE*16*NC];
__device__ float g_feat[NB*NE*NC];               // max-pooled conv4 relu (fp32)
__device__ float g_kT[3][NB][9][64][64];         // raw weights transposed to [co][ci] (fp32)
__device__ __nv_bfloat16 g_kBh[3][NB][9][64][64];// scale-folded split weights hi
__device__ __nv_bfloat16 g_kBl[3][NB][9][64][64];// scale-folded split weights lo
__device__ float g_C[3][NB][9][64];              // per-tap bias dot products
__device__ float g_sum[4*NC];
__device__ float g_sumsq[4*NC];
__device__ float g_scale[4*NC];                  // rsqrt(var+eps)
__device__ float g_bias[4*NC];                   // -mean*scale

__device__ __forceinline__ uint32_t smem_u32(const void* p) {
    return (uint32_t)__cvta_generic_to_shared(p);
}
__device__ __forceinline__ uint32_t pb(__nv_bfloat16 a, __nv_bfloat16 b) {
    unsigned short ua = *(unsigned short*)&a, ub = *(unsigned short*)&b;
    return (uint32_t)ua | ((uint32_t)ub << 16);
}

#define MMA_BF16(acc, A0,A1,A2,A3, B0,B1) \
    asm volatile("mma.sync.aligned.m16n8k16.row.col.f32.bf16.bf16.f32 " \
        "{%0,%1,%2,%3}, {%4,%5,%6,%7}, {%8,%9}, {%0,%1,%2,%3};" \
        : "+f"(acc[0]),"+f"(acc[1]),"+f"(acc[2]),"+f"(acc[3]) \
        : "r"(A0),"r"(A1),"r"(A2),"r"(A3), "r"(B0),"r"(B1))

#define LDMATRIX_X4(r0,r1,r2,r3, addr) \
    asm volatile("ldmatrix.sync.aligned.m8n8.x4.shared.b16 {%0,%1,%2,%3}, [%4];" \
        : "=r"(r0),"=r"(r1),"=r"(r2),"=r"(r3) : "r"(addr))

#define LDS32(r, addr) \
    asm volatile("ld.shared.b32 %0, [%1];" : "=r"(r) : "r"(addr))

// ---------------- zero stats + feat ----------------
__global__ void zero_kernel() {
    int i = blockIdx.x * 256 + threadIdx.x;
    if (i < 4*NC) { g_sum[i] = 0.f; g_sumsq[i] = 0.f; }
    if (i < NB*NE*NC) g_feat[i] = 0.f;
}

// ---------------- weight transpose: kw[b][kk][ci][co] -> g_kT[layer][b][kk][co][ci] ----------------
__global__ __launch_bounds__(256) void wtrans_kernel(const float* __restrict__ k2,
                                                     const float* __restrict__ k3,
                                                     const float* __restrict__ k4) {
    __shared__ float s[64*65];
    int layer = blockIdx.y;
    const float* kw = (layer==0) ? k2 : (layer==1) ? k3 : k4;
    int b  = blockIdx.x >> 4;
    int kk = blockIdx.x & 15;
    if (kk >= 9) return;
    int t = threadIdx.x;
    const float* src = kw + ((size_t)b*9 + kk)*4096;
    #pragma unroll
    for (int p = 0; p < 16; p++) {
        int idx = p*256 + t;           // idx = ci*64 + co
        int ci = idx >> 6, co = idx & 63;
        s[co*65 + ci] = src[idx];
    }
    __syncthreads();
    float* dst = &g_kT[layer][b][kk][0][0];
    #pragma unroll
    for (int p = 0; p < 16; p++) {
        int idx = p*256 + t;           // idx = co*64 + ci
        int co = idx >> 6, ci = idx & 63;
        dst[idx] = s[co*65 + ci];
    }
}

// ---------------- weight prep: fold BN scale of prev layer, split bf16, bias dots ----------------
// prepares conv layer (layer+1): W' = W * scale[layer][ci]; C[co] = sum_ci bias[layer][ci]*W[co][ci]
__global__ __launch_bounds__(256) void wprep_kernel(int layer) {
    __shared__ float s_C[64];
    int blk = blockIdx.x;
    int b = blk / 9, kk = blk - b*9;
    int t = threadIdx.x, lane = t & 31;
    if (t < 64) s_C[t] = 0.f;
    __syncthreads();
    const float* W = &g_kT[layer][b][kk][0][0];
    __nv_bfloat16* Dh = &g_kBh[layer][b][kk][0][0];
    __nv_bfloat16* Dl = &g_kBl[layer][b][kk][0][0];
    int ci = t & 63;
    float sc = g_scale[layer*64 + ci];
    float bb = g_bias[layer*64 + ci];
    #pragma unroll
    for (int e = 0; e < 16; e++) {
        int idx = e*256 + t;           // = co*64 + ci
        int co = idx >> 6;
        float w = W[idx];
        float ws = w * sc;
        __nv_bfloat16 hi = __float2bfloat16(ws);
        __nv_bfloat16 lo = __float2bfloat16(ws - __bfloat162float(hi));
        Dh[idx] = hi; Dl[idx] = lo;
        float c = bb * w;
        #pragma unroll
        for (int o = 16; o; o >>= 1) c += __shfl_down_sync(0xFFFFFFFFu, c, o);
        if (lane == 0) atomicAdd(&s_C[co], c);
    }
    __syncthreads();
    if (t < 64) g_C[layer][b][kk][t] = s_C[t];
}

// ---------------- conv1: Cin=1, 28x28 -> 14x14x64, split bf16 output ----------------
__global__ __launch_bounds__(256) void conv1_kernel(const float* __restrict__ x,
                                                    const float* __restrict__ k1) {
    __shared__ float s_in[30*30];
    __shared__ float s_sum[NC];
    __shared__ float s_sq[NC];
    int be = blockIdx.x;
    int t = threadIdx.x;
    for (int i = t; i < 900; i += 256) s_in[i] = 0.f;
    if (t < NC) { s_sum[t] = 0.f; s_sq[t] = 0.f; }
    __syncthreads();
    const float* xp = x + (size_t)be * 784;
    for (int i = t; i < 784; i += 256) {
        int r = i / 28, c = i - r*28;
        s_in[(r+1)*30 + c + 1] = xp[i];
    }
    int cg = t & 15, ig = t >> 4;
    int b = be >> 6;
    float4 w[9];
    const float4* kp = (const float4*)(k1 + (size_t)b * 576);
    #pragma unroll
    for (int j = 0; j < 9; j++) w[j] = kp[j*16 + cg];
    __syncthreads();
    float ls0=0,ls1=0,ls2=0,ls3=0, lq0=0,lq1=0,lq2=0,lq3=0;
    __nv_bfloat16* oh = g_h1h + (size_t)be * 196 * 64;
    __nv_bfloat16* ol = g_h1l + (size_t)be * 196 * 64;
    for (int p = ig; p < 196; p += 16) {
        int oy = p / 14, ox = p - oy*14;
        float a0=0,a1=0,a2=0,a3=0;
        #pragma unroll
        for (int ky = 0; ky < 3; ky++)
        #pragma unroll
        for (int kx = 0; kx < 3; kx++) {
            float v = s_in[(2*oy+ky)*30 + 2*ox + kx];
            float4 ww = w[ky*3+kx];
            a0 = fmaf(v, ww.x, a0); a1 = fmaf(v, ww.y, a1);
            a2 = fmaf(v, ww.z, a2); a3 = fmaf(v, ww.w, a3);
        }
        a0 = fmaxf(a0, 0.f); a1 = fmaxf(a1, 0.f);
        a2 = fmaxf(a2, 0.f); a3 = fmaxf(a3, 0.f);
        ls0+=a0; ls1+=a1; ls2+=a2; ls3+=a3;
        lq0+=a0*a0; lq1+=a1*a1; lq2+=a2*a2; lq3+=a3*a3;
        __nv_bfloat16 h0=__float2bfloat16(a0), h1=__float2bfloat16(a1),
                      h2=__float2bfloat16(a2), h3=__float2bfloat16(a3);
        __nv_bfloat16 l0=__float2bfloat16(a0-__bfloat162float(h0)),
                      l1=__float2bfloat16(a1-__bfloat162float(h1)),
                      l2=__float2bfloat16(a2-__bfloat162float(h2)),
                      l3=__float2bfloat16(a3-__bfloat162float(h3));
        ((uint2*)(oh + p*64))[cg] = make_uint2(pb(h0,h1), pb(h2,h3));
        ((uint2*)(ol + p*64))[cg] = make_uint2(pb(l0,l1), pb(l2,l3));
    }
    int co4 = cg*4;
    atomicAdd(&s_sum[co4+0], ls0); atomicAdd(&s_sum[co4+1], ls1);
    atomicAdd(&s_sum[co4+2], ls2); atomicAdd(&s_sum[co4+3], ls3);
    atomicAdd(&s_sq[co4+0], lq0); atomicAdd(&s_sq[co4+1], lq1);
    atomicAdd(&s_sq[co4+2], lq2); atomicAdd(&s_sq[co4+3], lq3);
    __syncthreads();
    if (t < NC) {
        atomicAdd(&g_sum[t], s_sum[t]);
        atomicAdd(&g_sumsq[t], s_sq[t]);
    }
}

// ---------------- per-layer BN stats finalize ----------------
__global__ void finalize_kernel(int layer, float invN) {
    int c = threadIdx.x;
    float s = g_sum[layer*NC + c];
    float q = g_sumsq[layer*NC + c];
    float m = s * invN;
    float v = q * invN - m*m;
    float sc = rsqrtf(v + 1e-3f);
    g_scale[layer*NC + c] = sc;
    g_bias[layer*NC + c] = -m * sc;
}

// ---------------- conv layers 2-4: mma.sync bf16-split, pure-copy loaders ----------------
// A = pre-split activations (hi/lo planes), B = pre-scaled split weights, bias via s_bias table.
template<int LNUM>
__global__ __launch_bounds__(256, 2) void conv_kernel() {
    constexpr int HIN  = (LNUM==1) ? 14 : (LNUM==2) ? 7 : 4;
    constexpr int HOUT = (LNUM==1) ? 7  : (LNUM==2) ? 4 : 2;
    constexpr bool LAST = (LNUM==3);
    constexpr int POS   = HOUT*HOUT;
    constexpr int MTASK = NE*POS;
    constexpr int RS    = 144;                 // smem row stride bytes (72 bf16)
    constexpr int AHI_O = 0, ALO_O = 128*RS, BHI_O = 2*128*RS, BLO_O = BHI_O + 64*RS;
    constexpr int BIAS_O = BHI_O + 2*64*RS;

    __shared__ float s_sum[64], s_sq[64];
    __shared__ int s_ri[128];
    extern __shared__ char dsm[];
    float* s_bias = (float*)(dsm + BIAS_O);

    int b = blockIdx.y, m0 = blockIdx.x*128, t = threadIdx.x;
    int wid = t >> 5, lane = t & 31;

    if (t < 64) { s_sum[t] = 0.f; s_sq[t] = 0.f; }
    if (t < 128) {
        int gic = min(m0 + t, MTASK-1);
        int e = gic / POS, p = gic - e*POS;
        s_ri[t] = (e << 16) | ((p / HOUT) << 8) | (p % HOUT);
    }
    // per-position bias table: sum of C[kk][co] over in-bounds taps
    {
        const float* Cb = &g_C[LNUM-1][b][0][0];
        for (int idx = t; idx < POS*64; idx += 256) {
            int p = idx >> 6, co = idx & 63;
            int oy = p / HOUT, ox = p - oy*HOUT;
            float s = 0.f;
            #pragma unroll
            for (int ky = 0; ky < 3; ky++) {
                int iy = 2*oy - 1 + ky;
                if ((unsigned)iy >= (unsigned)HIN) continue;
                #pragma unroll
                for (int kx = 0; kx < 3; kx++) {
                    int ix = 2*ox - 1 + kx;
                    if ((unsigned)ix < (unsigned)HIN) s += Cb[(ky*3+kx)*64 + co];
                }
            }
            s_bias[idx] = s;
        }
    }
    __syncthreads();

    const __nv_bfloat16* ph = ((LNUM==1) ? g_h1h : (LNUM==2) ? g_h2h : g_h3h)
                            + (size_t)b*NE*HIN*HIN*64;
    const __nv_bfloat16* pl = ((LNUM==1) ? g_h1l : (LNUM==2) ? g_h2l : g_h3l)
                            + (size_t)b*NE*HIN*HIN*64;
    __nv_bfloat16* oh = (LNUM==1) ? g_h2h : g_h3h;
    __nv_bfloat16* ol = (LNUM==1) ? g_h2l : g_h3l;

    // A loader: 16 threads per row; lj<8 -> hi plane seg lj, lj>=8 -> lo plane seg lj-8
    int lr = t >> 4, lj = t & 15;
    bool hiP = lj < 8;
    int seg = lj & 7;
    const __nv_bfloat16* planeA = hiP ? ph : pl;
    int adst = (hiP ? AHI_O : ALO_O) + seg*16;

    // mma addressing
    uint32_t smem0 = smem_u32(dsm);
    uint32_t a_base = smem0 + AHI_O + (wid*16)*RS + (lane & 15)*RS + ((lane >> 4) * 16);
    uint32_t b_base = smem0 + BHI_O + (lane >> 2)*RS + (lane & 3)*4;

    float acc[8][4];
    #pragma unroll
    for (int nt = 0; nt < 8; nt++)
        #pragma unroll
        for (int j = 0; j < 4; j++) acc[nt][j] = 0.f;

    for (int kk = 0; kk < 9; kk++) {
        int ky = kk/3, kx = kk - ky*3;
        // ---- B tile: pure copy of pre-scaled split weights ----
        {
            const uint4* sBh = (const uint4*)&g_kBh[LNUM-1][b][kk][0][0];
            const uint4* sBl = (const uint4*)&g_kBl[LNUM-1][b][kk][0][0];
            #pragma unroll
            for (int p = 0; p < 4; p++) {
                int idx = p*256 + t;
                int row = idx >> 4, l = idx & 15;
                bool hp = l < 8; int sg = l & 7;
                uint4 v = hp ? sBh[row*8 + sg] : sBl[row*8 + sg];
                *(uint4*)(dsm + (hp ? BHI_O : BLO_O) + row*RS + sg*16) = v;
            }
        }
        // ---- A tile: pure copy im2col gather from split planes ----
        #pragma unroll
        for (int rr = 0; rr < 8; rr++) {
            int row = rr*16 + lr;
            int info = s_ri[row];
            int e = info >> 16, oy = (info >> 8) & 255, ox = info & 255;
            int iy = 2*oy - 1 + ky;
            int ix = 2*ox - 1 + kx;
            uint4 v = make_uint4(0u,0u,0u,0u);
            if ((unsigned)iy < (unsigned)HIN && (unsigned)ix < (unsigned)HIN)
                v = ((const uint4*)(planeA + ((size_t)e*HIN*HIN + iy*HIN + ix)*64))[seg];
            *(uint4*)(dsm + adst + row*RS) = v;
        }
        __syncthreads();
        // ---- MMA: 4 k16-steps; per step: A frags (hi,lo) + 8 n-tiles x 3 terms ----
        #pragma unroll
        for (int ks = 0; ks < 4; ks++) {
            uint32_t ah0,ah1,ah2,ah3, al0,al1,al2,al3;
            LDMATRIX_X4(ah0,ah1,ah2,ah3, a_base + ks*32);
            LDMATRIX_X4(al0,al1,al2,al3, a_base + (ALO_O - AHI_O) + ks*32);
            #pragma unroll
            for (int nt = 0; nt < 8; nt++) {
                uint32_t bh0,bh1,bl0,bl1;
                uint32_t ba = b_base + nt*8*RS + ks*32;
                LDS32(bh0, ba);
                LDS32(bh1, ba + 16);
                LDS32(bl0, ba + (BLO_O - BHI_O));
                LDS32(bl1, ba + (BLO_O - BHI_O) + 16);
                MMA_BF16(acc[nt], ah0,ah1,ah2,ah3, bh0,bh1);
                MMA_BF16(acc[nt], ah0,ah1,ah2,ah3, bl0,bl1);
                MMA_BF16(acc[nt], al0,al1,al2,al3, bh0,bh1);
            }
        }
        __syncthreads();
    }

    // ---- epilogue: +bias, relu, BN stats, split-store / max-pool ----
    int q  = lane & 3;
    int r0 = lane >> 2;
    int g0 = m0 + wid*16 + r0;
    int g1 = g0 + 8;
    bool v0 = g0 < MTASK, v1 = g1 < MTASK;
    int e0 = g0 / POS, p0 = g0 - e0*POS;
    int e1 = g1 / POS, p1 = g1 - e1*POS;
    float lsum[16], lsq[16];
    #pragma unroll
    for (int nt = 0; nt < 8; nt++) {
        int col = nt*8 + q*2;
        float d0 = v0 ? fmaxf(acc[nt][0] + s_bias[p0*64+col],   0.f) : 0.f;
        float d1 = v0 ? fmaxf(acc[nt][1] + s_bias[p0*64+col+1], 0.f) : 0.f;
        float d2 = v1 ? fmaxf(acc[nt][2] + s_bias[p1*64+col],   0.f) : 0.f;
        float d3 = v1 ? fmaxf(acc[nt][3] + s_bias[p1*64+col+1], 0.f) : 0.f;
        lsum[2*nt]   = d0 + d2;  lsq[2*nt]   = d0*d0 + d2*d2;
        lsum[2*nt+1] = d1 + d3;  lsq[2*nt+1] = d1*d1 + d3*d3;
        if (!LAST) {
            if (v0) {
                __nv_bfloat16 h0=__float2bfloat16(d0), h1=__float2bfloat16(d1);
                __nv_bfloat16 l0=__float2bfloat16(d0-__bfloat162float(h0)),
                              l1=__float2bfloat16(d1-__bfloat162float(h1));
                size_t o = ((size_t)b*MTASK + g0)*64 + col;
                *(uint32_t*)(oh + o) = pb(h0,h1);
                *(uint32_t*)(ol + o) = pb(l0,l1);
            }
            if (v1) {
                __nv_bfloat16 h2=__float2bfloat16(d2), h3=__float2bfloat16(d3);
                __nv_bfloat16 l2=__float2bfloat16(d2-__bfloat162float(h2)),
                              l3=__float2bfloat16(d3-__bfloat162float(h3));
                size_t o = ((size_t)b*MTASK + g1)*64 + col;
                *(uint32_t*)(oh + o) = pb(h2,h3);
                *(uint32_t*)(ol + o) = pb(l2,l3);
            }
        } else {
            if (v0) {
                int* fp = (int*)(g_feat + (size_t)(b*NE + e0)*64 + col);
                atomicMax(&fp[0], __float_as_int(d0));
                atomicMax(&fp[1], __float_as_int(d1));
            }
            if (v1) {
                int* fp = (int*)(g_feat + (size_t)(b*NE + e1)*64 + col);
                atomicMax(&fp[0], __float_as_int(d2));
                atomicMax(&fp[1], __float_as_int(d3));
            }
        }
    }
    #pragma unroll
    for (int j = 0; j < 16; j++) {
        #pragma unroll
        for (int o = 4; o <= 16; o <<= 1) {
            lsum[j] += __shfl_xor_sync(0xFFFFFFFFu, lsum[j], o);
            lsq[j]  += __shfl_xor_sync(0xFFFFFFFFu, lsq[j],  o);
        }
    }
    if (lane < 4) {
        #pragma unroll
        for (int nt = 0; nt < 8; nt++) {
            int col = nt*8 + q*2;
            atomicAdd(&s_sum[col],   lsum[2*nt]);
            atomicAdd(&s_sum[col+1], lsum[2*nt+1]);
            atomicAdd(&s_sq[col],    lsq[2*nt]);
            atomicAdd(&s_sq[col+1],  lsq[2*nt+1]);
        }
    }
    __syncthreads();
    if (t < 64) {
        atomicAdd(&g_sum[LNUM*NC + t],   s_sum[t]);
        atomicAdd(&g_sumsq[LNUM*NC + t], s_sq[t]);
    }
}

// ---------------- readout: normalize pooled feats, per-task matmul ----------------
__global__ __launch_bounds__(256) void readout_kernel(const float* __restrict__ w_ro,
                                                      float* __restrict__ out) {
    __shared__ float s_w[64*20];
    __shared__ float s_f[64*64];
    int b = blockIdx.x, t = threadIdx.x;
    for (int i = t; i < 1280; i += 256) s_w[i] = w_ro[(size_t)b*1280 + i];
    const float* fp = g_feat + (size_t)b*4096;
    for (int i = t; i < 4096; i += 256) {
        int c = i & 63;
        s_f[i] = fmaf(fp[i], g_scale[3*64+c], g_bias[3*64+c]);
    }
    __syncthreads();
    for (int idx = t; idx < 1280; idx += 256) {
        int e = idx/20, o = idx - e*20;
        float s = 0.f;
        const float* fe = s_f + e*64;
        #pragma unroll 16
        for (int c = 0; c < 64; c++) s = fmaf(fe[c], s_w[c*20+o], s);
        out[(size_t)b*1280 + idx] = s;
    }
}

// ---------------- launch ----------------
extern "C" void kernel_launch(void* const* d_in, const int* in_sizes, int n_in,
                              void* d_out, int out_size) {
    const float* x  = (const float*)d_in[0];
    const float* k1 = (const float*)d_in[1];
    const float* k2 = (const float*)d_in[2];
    const float* k3 = (const float*)d_in[3];
    const float* k4 = (const float*)d_in[4];
    const float* w  = (const float*)d_in[5];
    float* out = (float*)d_out;
    (void)in_sizes; (void)n_in; (void)out_size;

    const int base = 2*128*144 + 2*64*144;         // A hi/lo + B hi/lo = 55296
    const int dsm1 = base + 49*64*4;               // + bias table
    const int dsm2 = base + 16*64*4;
    const int dsm3 = base + 4*64*4;
    cudaFuncSetAttribute(conv_kernel<1>, cudaFuncAttributeMaxDynamicSharedMemorySize, dsm1);
    cudaFuncSetAttribute(conv_kernel<2>, cudaFuncAttributeMaxDynamicSharedMemorySize, dsm2);
    cudaFuncSetAttribute(conv_kernel<3>, cudaFuncAttributeMaxDynamicSharedMemorySize, dsm3);

    zero_kernel<<<1024, 256>>>();
    wtrans_kernel<<<dim3(64*16, 3), 256>>>(k2, k3, k4);
    conv1_kernel<<<NB*NE, 256>>>(x, k1);
    finalize_kernel<<<1, 64>>>(0, 1.f/(NB*NE*196.f));
    wprep_kernel<<<576, 256>>>(0);
    conv_kernel<1><<<dim3(25, NB), 256, dsm1>>>();
    finalize_kernel<<<1, 64>>>(1, 1.f/(NB*NE*49.f));
    wprep_kernel<<<576, 256>>>(1);
    conv_kernel<2><<<dim3(8, NB), 256, dsm2>>>();
    finalize_kernel<<<1, 64>>>(2, 1.f/(NB*NE*16.f));
    wprep_kernel<<<576, 256>>>(2);
    conv_kernel<3><<<dim3(2, NB), 256, dsm3>>>();
    finalize_kernel<<<1, 64>>>(3, 1.f/(NB*NE*4.f));
    readout_kernel<<<NB, 256>>>(w, out);
}

// round 12
// speedup vs baseline: 1.7062x; 1.7062x over previous
#include <cuda_runtime.h>
#include <cuda_bf16.h>
#include <cstdint>

#define NB 64
#define NE 64
#define NC 64
#define NO 20

// ---------------- device scratch (no allocs allowed) ----------------
__device__ __align__(128) __nv_bfloat16 g_h1h[(size_t)NB*NE*196*NC], g_h1l[(size_t)NB*NE*196*NC];
__device__ __align__(128) __nv_bfloat16 g_h2h[(size_t)NB*NE*49*NC],  g_h2l[(size_t)NB*NE*49*NC];
__device__ __align__(128) __nv_bfloat16 g_h3h[(size_t)NB*NE*16*NC],  g_h3l[(size_t)NB*NE*16*NC];
__device__ float g_feat[NB*NE*NC];
__device__ __align__(128) __nv_bfloat16 g_kBh[3][NB][9][64][64];  // scale-folded split weights [co][ci]
__device__ __align__(128) __nv_bfloat16 g_kBl[3][NB][9][64][64];
__device__ float g_C[3][NB][9][64];              // per-tap bias dot products
__device__ float g_sum[4*NC];
__device__ float g_sumsq[4*NC];
__device__ float g_scale[4*NC];
__device__ float g_bias[4*NC];

__device__ __forceinline__ uint32_t smem_u32(const void* p) {
    return (uint32_t)__cvta_generic_to_shared(p);
}
__device__ __forceinline__ uint32_t pb(__nv_bfloat16 a, __nv_bfloat16 b) {
    unsigned short ua = *(unsigned short*)&a, ub = *(unsigned short*)&b;
    return (uint32_t)ua | ((uint32_t)ub << 16);
}

#define MMA_BF16(acc, A0,A1,A2,A3, B0,B1) \
    asm volatile("mma.sync.aligned.m16n8k16.row.col.f32.bf16.bf16.f32 " \
        "{%0,%1,%2,%3}, {%4,%5,%6,%7}, {%8,%9}, {%0,%1,%2,%3};" \
        : "+f"(acc[0]),"+f"(acc[1]),"+f"(acc[2]),"+f"(acc[3]) \
        : "r"(A0),"r"(A1),"r"(A2),"r"(A3), "r"(B0),"r"(B1))

#define LDMATRIX_X4(r0,r1,r2,r3, addr) \
    asm volatile("ldmatrix.sync.aligned.m8n8.x4.shared.b16 {%0,%1,%2,%3}, [%4];" \
        : "=r"(r0),"=r"(r1),"=r"(r2),"=r"(r3) : "r"(addr))

#define LDS32(r, addr) \
    asm volatile("ld.shared.b32 %0, [%1];" : "=r"(r) : "r"(addr))

#define CP16(dst, src, sz) \
    asm volatile("cp.async.ca.shared.global [%0], [%1], 16, %2;" \
        :: "r"(dst), "l"(src), "r"(sz))
#define CP_COMMIT() asm volatile("cp.async.commit_group;")
#define CP_WAIT1()  asm volatile("cp.async.wait_group 1;")
#define CP_WAIT0()  asm volatile("cp.async.wait_group 0;")

// ---------------- zero stats + feat ----------------
__global__ void zero_kernel() {
    int i = blockIdx.x * 256 + threadIdx.x;
    if (i < 4*NC) { g_sum[i] = 0.f; g_sumsq[i] = 0.f; }
    if (i < NB*NE*NC) g_feat[i] = 0.f;
}

// ---------------- wprep: transpose + BN-scale fold + bf16 split + bias dots ----------------
__global__ __launch_bounds__(256) void wprep_kernel(const float* __restrict__ kw, int layer) {
    __shared__ float s[64*65];
    __shared__ float s_C[64];
    int blk = blockIdx.x;
    int b = blk / 9, kk = blk - b*9;
    int t = threadIdx.x, lane = t & 31;
    if (t < 64) s_C[t] = 0.f;
    const float* src = kw + ((size_t)b*9 + kk)*4096;
    #pragma unroll
    for (int p = 0; p < 16; p++) {
        int idx = p*256 + t;           // = ci*64 + co
        int ci = idx >> 6, co = idx & 63;
        s[co*65 + ci] = src[idx];
    }
    __syncthreads();
    int ci = t & 63;
    float sc = g_scale[layer*64 + ci];
    float bb = g_bias[layer*64 + ci];
    __nv_bfloat16* Dh = &g_kBh[layer][b][kk][0][0];
    __nv_bfloat16* Dl = &g_kBl[layer][b][kk][0][0];
    #pragma unroll
    for (int e = 0; e < 16; e++) {
        int idx = e*256 + t;           // = co*64 + ci
        int co = idx >> 6;
        float w = s[co*65 + ci];
        float ws = w * sc;
        __nv_bfloat16 hi = __float2bfloat16(ws);
        __nv_bfloat16 lo = __float2bfloat16(ws - __bfloat162float(hi));
        Dh[idx] = hi; Dl[idx] = lo;
        float c = bb * w;
        #pragma unroll
        for (int o = 16; o; o >>= 1) c += __shfl_down_sync(0xFFFFFFFFu, c, o);
        if (lane == 0) atomicAdd(&s_C[co], c);
    }
    __syncthreads();
    if (t < 64) g_C[layer][b][kk][t] = s_C[t];
}

// ---------------- conv1: Cin=1, 28x28 -> 14x14x64, split bf16 output ----------------
__global__ __launch_bounds__(256) void conv1_kernel(const float* __restrict__ x,
                                                    const float* __restrict__ k1) {
    __shared__ float s_in[30*30];
    __shared__ float s_sum[NC];
    __shared__ float s_sq[NC];
    int be = blockIdx.x;
    int t = threadIdx.x;
    for (int i = t; i < 900; i += 256) s_in[i] = 0.f;
    if (t < NC) { s_sum[t] = 0.f; s_sq[t] = 0.f; }
    __syncthreads();
    const float* xp = x + (size_t)be * 784;
    for (int i = t; i < 784; i += 256) {
        int r = i / 28, c = i - r*28;
        s_in[(r+1)*30 + c + 1] = xp[i];
    }
    int cg = t & 15, ig = t >> 4;
    int b = be >> 6;
    float4 w[9];
    const float4* kp = (const float4*)(k1 + (size_t)b * 576);
    #pragma unroll
    for (int j = 0; j < 9; j++) w[j] = kp[j*16 + cg];
    __syncthreads();
    float ls0=0,ls1=0,ls2=0,ls3=0, lq0=0,lq1=0,lq2=0,lq3=0;
    __nv_bfloat16* oh = g_h1h + (size_t)be * 196 * 64;
    __nv_bfloat16* ol = g_h1l + (size_t)be * 196 * 64;
    for (int p = ig; p < 196; p += 16) {
        int oy = p / 14, ox = p - oy*14;
        float a0=0,a1=0,a2=0,a3=0;
        #pragma unroll
        for (int ky = 0; ky < 3; ky++)
        #pragma unroll
        for (int kx = 0; kx < 3; kx++) {
            float v = s_in[(2*oy+ky)*30 + 2*ox + kx];
            float4 ww = w[ky*3+kx];
            a0 = fmaf(v, ww.x, a0); a1 = fmaf(v, ww.y, a1);
            a2 = fmaf(v, ww.z, a2); a3 = fmaf(v, ww.w, a3);
        }
        a0 = fmaxf(a0, 0.f); a1 = fmaxf(a1, 0.f);
        a2 = fmaxf(a2, 0.f); a3 = fmaxf(a3, 0.f);
        ls0+=a0; ls1+=a1; ls2+=a2; ls3+=a3;
        lq0+=a0*a0; lq1+=a1*a1; lq2+=a2*a2; lq3+=a3*a3;
        __nv_bfloat16 h0=__float2bfloat16(a0), h1=__float2bfloat16(a1),
                      h2=__float2bfloat16(a2), h3=__float2bfloat16(a3);
        __nv_bfloat16 l0=__float2bfloat16(a0-__bfloat162float(h0)),
                      l1=__float2bfloat16(a1-__bfloat162float(h1)),
                      l2=__float2bfloat16(a2-__bfloat162float(h2)),
                      l3=__float2bfloat16(a3-__bfloat162float(h3));
        ((uint2*)(oh + p*64))[cg] = make_uint2(pb(h0,h1), pb(h2,h3));
        ((uint2*)(ol + p*64))[cg] = make_uint2(pb(l0,l1), pb(l2,l3));
    }
    int co4 = cg*4;
    atomicAdd(&s_sum[co4+0], ls0); atomicAdd(&s_sum[co4+1], ls1);
    atomicAdd(&s_sum[co4+2], ls2); atomicAdd(&s_sum[co4+3], ls3);
    atomicAdd(&s_sq[co4+0], lq0); atomicAdd(&s_sq[co4+1], lq1);
    atomicAdd(&s_sq[co4+2], lq2); atomicAdd(&s_sq[co4+3], lq3);
    __syncthreads();
    if (t < NC) {
        atomicAdd(&g_sum[t], s_sum[t]);
        atomicAdd(&g_sumsq[t], s_sq[t]);
    }
}

// ---------------- per-layer BN stats finalize ----------------
__global__ void finalize_kernel(int layer, float invN) {
    int c = threadIdx.x;
    float s = g_sum[layer*NC + c];
    float q = g_sumsq[layer*NC + c];
    float m = s * invN;
    float v = q * invN - m*m;
    float sc = rsqrtf(v + 1e-3f);
    g_scale[layer*NC + c] = sc;
    g_bias[layer*NC + c] = -m * sc;
}

// ---------------- conv layers 2-4: double-buffered cp.async + mma.sync bf16-split ----------------
// M-tile 64 (exact), 8 warps = 4 m16-tiles x 2 n32-halves. 2-stage pipeline.
template<int LNUM>
__global__ __launch_bounds__(256, 2) void conv_kernel() {
    constexpr int HIN  = (LNUM==1) ? 14 : (LNUM==2) ? 7 : 4;
    constexpr int HOUT = (LNUM==1) ? 7  : (LNUM==2) ? 4 : 2;
    constexpr bool LAST = (LNUM==3);
    constexpr int POS   = HOUT*HOUT;
    constexpr int MTASK = NE*POS;
    constexpr int RS    = 144;
    constexpr int A_HI = 0, A_LO = 64*RS, B_HI = 2*64*RS, B_LO = 3*64*RS;
    constexpr int STAGE = 4*64*RS;       // 36864
    constexpr int BIAS_O = 2*STAGE;

    __shared__ float s_sum[64], s_sq[64];
    __shared__ int s_ri[64];
    extern __shared__ char dsm[];
    float* s_bias = (float*)(dsm + BIAS_O);

    int b = blockIdx.y, m0 = blockIdx.x*64, t = threadIdx.x;
    int wid = t >> 5, lane = t & 31;

    if (t < 64) {
        s_sum[t] = 0.f; s_sq[t] = 0.f;
        int gic = m0 + t;
        int e = gic / POS, p = gic - e*POS;
        s_ri[t] = (e << 16) | ((p / HOUT) << 8) | (p % HOUT);
    }
    {
        const float* Cb = &g_C[LNUM-1][b][0][0];
        for (int idx = t; idx < POS*64; idx += 256) {
            int p = idx >> 6, co = idx & 63;
            int oy = p / HOUT, ox = p - oy*HOUT;
            float s = 0.f;
            #pragma unroll
            for (int ky = 0; ky < 3; ky++) {
                int iy = 2*oy - 1 + ky;
                if ((unsigned)iy >= (unsigned)HIN) continue;
                #pragma unroll
                for (int kx = 0; kx < 3; kx++) {
                    int ix = 2*ox - 1 + kx;
                    if ((unsigned)ix < (unsigned)HIN) s += Cb[(ky*3+kx)*64 + co];
                }
            }
            s_bias[idx] = s;
        }
    }
    __syncthreads();

    const __nv_bfloat16* ph = ((LNUM==1) ? g_h1h : (LNUM==2) ? g_h2h : g_h3h)
                            + (size_t)b*NE*HIN*HIN*64;
    const __nv_bfloat16* pl = ((LNUM==1) ? g_h1l : (LNUM==2) ? g_h2l : g_h3l)
                            + (size_t)b*NE*HIN*HIN*64;
    __nv_bfloat16* oh = (LNUM==1) ? g_h2h : g_h3h;
    __nv_bfloat16* ol = (LNUM==1) ? g_h2l : g_h3l;
    const char* phc = (const char*)ph;
    const char* plc = (const char*)pl;
    const char* Bhc = (const char*)&g_kBh[LNUM-1][b][0][0][0];
    const char* Blc = (const char*)&g_kBl[LNUM-1][b][0][0][0];

    // loader precompute: thread covers rows r0 = t>>3 and r0+32 of each sub-tile, seg = t&7
    int seg = t & 7, r0 = t >> 3, r1 = r0 + 32;
    int inf0 = s_ri[r0], inf1 = s_ri[r1];
    int e0 = inf0 >> 16, iyb0 = 2*((inf0 >> 8) & 255) - 1, ixb0 = 2*(inf0 & 255) - 1;
    int e1 = inf1 >> 16, iyb1 = 2*((inf1 >> 8) & 255) - 1, ixb1 = 2*(inf1 & 255) - 1;
    int ab0 = e0*HIN*HIN*128 + seg*16;   // byte offsets into activation planes
    int ab1 = e1*HIN*HIN*128 + seg*16;
    uint32_t dA0 = A_HI + r0*RS + seg*16, dA1 = A_HI + r1*RS + seg*16;
    uint32_t dB0 = B_HI + r0*RS + seg*16, dB1 = B_HI + r1*RS + seg*16;
    int rbB0 = r0*128 + seg*16, rbB1 = r1*128 + seg*16;

    uint32_t smem0 = smem_u32(dsm);

    auto issue = [&](int kk, uint32_t sb) {
        int ky = kk/3, kx = kk - (kk/3)*3;
        int iy0 = iyb0 + ky, ix0 = ixb0 + kx;
        int iy1 = iyb1 + ky, ix1 = ixb1 + kx;
        bool v0 = (unsigned)iy0 < (unsigned)HIN && (unsigned)ix0 < (unsigned)HIN;
        bool v1 = (unsigned)iy1 < (unsigned)HIN && (unsigned)ix1 < (unsigned)HIN;
        int o0 = v0 ? (ab0 + (iy0*HIN + ix0)*128) : 0;
        int o1 = v1 ? (ab1 + (iy1*HIN + ix1)*128) : 0;
        int s0 = v0 ? 16 : 0, s1 = v1 ? 16 : 0;
        CP16(sb + dA0,                 phc + o0, s0);
        CP16(sb + dA1,                 phc + o1, s1);
        CP16(sb + dA0 + (A_LO - A_HI), plc + o0, s0);
        CP16(sb + dA1 + (A_LO - A_HI), plc + o1, s1);
        int bo = kk*8192;
        CP16(sb + dB0,                 Bhc + bo + rbB0, 16);
        CP16(sb + dB1,                 Bhc + bo + rbB1, 16);
        CP16(sb + dB0 + (B_LO - B_HI), Blc + bo + rbB0, 16);
        CP16(sb + dB1 + (B_LO - B_HI), Blc + bo + rbB1, 16);
    };

    int mw = wid & 3, ntb = (wid >> 2) * 4;
    float acc[4][4];
    #pragma unroll
    for (int nt = 0; nt < 4; nt++)
        #pragma unroll
        for (int j = 0; j < 4; j++) acc[nt][j] = 0.f;

    auto domma = [&](uint32_t sb) {
        uint32_t a_base = sb + A_HI + mw*(16*RS) + (lane & 15)*RS + ((lane >> 4) * 16);
        uint32_t b_base = sb + B_HI + (ntb*8 + (lane >> 2))*RS + (lane & 3)*4;
        #pragma unroll
        for (int ks = 0; ks < 4; ks++) {
            uint32_t ah0,ah1,ah2,ah3, al0,al1,al2,al3;
            LDMATRIX_X4(ah0,ah1,ah2,ah3, a_base + ks*32);
            LDMATRIX_X4(al0,al1,al2,al3, a_base + (A_LO - A_HI) + ks*32);
            #pragma unroll
            for (int nt = 0; nt < 4; nt++) {
                uint32_t ba = b_base + nt*(8*RS) + ks*32;
                uint32_t bh0,bh1,bl0,bl1;
                LDS32(bh0, ba);
                LDS32(bh1, ba + 16);
                LDS32(bl0, ba + (B_LO - B_HI));
                LDS32(bl1, ba + (B_LO - B_HI) + 16);
                MMA_BF16(acc[nt], ah0,ah1,ah2,ah3, bh0,bh1);
                MMA_BF16(acc[nt], ah0,ah1,ah2,ah3, bl0,bl1);
                MMA_BF16(acc[nt], al0,al1,al2,al3, bh0,bh1);
            }
        }
    };

    // ---- 2-stage pipeline over 9 chunks ----
    issue(0, smem0);
    CP_COMMIT();
    #pragma unroll
    for (int kk = 0; kk < 9; kk++) {
        if (kk < 8) {
            issue(kk+1, smem0 + ((kk+1) & 1)*STAGE);
            CP_COMMIT();
            CP_WAIT1();
        } else {
            CP_WAIT0();
        }
        __syncthreads();
        domma(smem0 + (kk & 1)*STAGE);
        __syncthreads();
    }

    // ---- epilogue: +bias, relu, stats, split-store / max-pool ----
    int q = lane & 3, r = lane >> 2;
    int g0 = m0 + mw*16 + r, g1 = g0 + 8;
    int E0 = g0 / POS, p0 = g0 - E0*POS;
    int E1 = g1 / POS, p1 = g1 - E1*POS;
    float lsum[8], lsq[8];
    #pragma unroll
    for (int nt = 0; nt < 4; nt++) {
        int col = (ntb + nt)*8 + q*2;
        float d0 = fmaxf(acc[nt][0] + s_bias[p0*64+col],   0.f);
        float d1 = fmaxf(acc[nt][1] + s_bias[p0*64+col+1], 0.f);
        float d2 = fmaxf(acc[nt][2] + s_bias[p1*64+col],   0.f);
        float d3 = fmaxf(acc[nt][3] + s_bias[p1*64+col+1], 0.f);
        lsum[2*nt]   = d0 + d2;  lsq[2*nt]   = d0*d0 + d2*d2;
        lsum[2*nt+1] = d1 + d3;  lsq[2*nt+1] = d1*d1 + d3*d3;
        if (!LAST) {
            {
                __nv_bfloat16 h0=__float2bfloat16(d0), h1=__float2bfloat16(d1);
                __nv_bfloat16 l0=__float2bfloat16(d0-__bfloat162float(h0)),
                              l1=__float2bfloat16(d1-__bfloat162float(h1));
                size_t o = ((size_t)b*MTASK + g0)*64 + col;
                *(uint32_t*)(oh + o) = pb(h0,h1);
                *(uint32_t*)(ol + o) = pb(l0,l1);
            }
            {
                __nv_bfloat16 h2=__float2bfloat16(d2), h3=__float2bfloat16(d3);
                __nv_bfloat16 l2=__float2bfloat16(d2-__bfloat162float(h2)),
                              l3=__float2bfloat16(d3-__bfloat162float(h3));
                size_t o = ((size_t)b*MTASK + g1)*64 + col;
                *(uint32_t*)(oh + o) = pb(h2,h3);
                *(uint32_t*)(ol + o) = pb(l2,l3);
            }
        } else {
            int* fp0 = (int*)(g_feat + (size_t)(b*NE + E0)*64 + col);
            atomicMax(&fp0[0], __float_as_int(d0));
            atomicMax(&fp0[1], __float_as_int(d1));
            int* fp1 = (int*)(g_feat + (size_t)(b*NE + E1)*64 + col);
            atomicMax(&fp1[0], __float_as_int(d2));
            atomicMax(&fp1[1], __float_as_int(d3));
        }
    }
    #pragma unroll
    for (int j = 0; j < 8; j++) {
        #pragma unroll
        for (int o = 4; o <= 16; o <<= 1) {
            lsum[j] += __shfl_xor_sync(0xFFFFFFFFu, lsum[j], o);
            lsq[j]  += __shfl_xor_sync(0xFFFFFFFFu, lsq[j],  o);
        }
    }
    if (lane < 4) {
        #pragma unroll
        for (int nt = 0; nt < 4; nt++) {
            int col = (ntb + nt)*8 + lane*2;
            atomicAdd(&s_sum[col],   lsum[2*nt]);
            atomicAdd(&s_sum[col+1], lsum[2*nt+1]);
            atomicAdd(&s_sq[col],    lsq[2*nt]);
            atomicAdd(&s_sq[col+1],  lsq[2*nt+1]);
        }
    }
    __syncthreads();
    if (t < 64) {
        atomicAdd(&g_sum[LNUM*NC + t],   s_sum[t]);
        atomicAdd(&g_sumsq[LNUM*NC + t], s_sq[t]);
    }
}

// ---------------- readout: normalize pooled feats, per-task matmul ----------------
__global__ __launch_bounds__(256) void readout_kernel(const float* __restrict__ w_ro,
                                                      float* __restrict__ out) {
    __shared__ float s_w[64*20];
    __shared__ float s_f[64*64];
    int b = blockIdx.x, t = threadIdx.x;
    for (int i = t; i < 1280; i += 256) s_w[i] = w_ro[(size_t)b*1280 + i];
    const float* fp = g_feat + (size_t)b*4096;
    for (int i = t; i < 4096; i += 256) {
        int c = i & 63;
        s_f[i] = fmaf(fp[i], g_scale[3*64+c], g_bias[3*64+c]);
    }
    __syncthreads();
    for (int idx = t; idx < 1280; idx += 256) {
        int e = idx/20, o = idx - e*20;
        float s = 0.f;
        const float* fe = s_f + e*64;
        #pragma unroll 16
        for (int c = 0; c < 64; c++) s = fmaf(fe[c], s_w[c*20+o], s);
        out[(size_t)b*1280 + idx] = s;
    }
}

// ---------------- launch ----------------
extern "C" void kernel_launch(void* const* d_in, const int* in_sizes, int n_in,
                              void* d_out, int out_size) {
    const float* x  = (const float*)d_in[0];
    const float* k1 = (const float*)d_in[1];
    const float* k2 = (const float*)d_in[2];
    const float* k3 = (const float*)d_in[3];
    const float* k4 = (const float*)d_in[4];
    const float* w  = (const float*)d_in[5];
    float* out = (float*)d_out;
    (void)in_sizes; (void)n_in; (void)out_size;

    const int STAGE2 = 2*4*64*144;                 // 73728
    const int dsm1 = STAGE2 + 49*64*4;             // 86272
    const int dsm2 = STAGE2 + 16*64*4;             // 77824
    const int dsm3 = STAGE2 + 4*64*4;              // 74752
    cudaFuncSetAttribute(conv_kernel<1>, cudaFuncAttributeMaxDynamicSharedMemorySize, dsm1);
    cudaFuncSetAttribute(conv_kernel<2>, cudaFuncAttributeMaxDynamicSharedMemorySize, dsm2);
    cudaFuncSetAttribute(conv_kernel<3>, cudaFuncAttributeMaxDynamicSharedMemorySize, dsm3);

    zero_kernel<<<1024, 256>>>();
    conv1_kernel<<<NB*NE, 256>>>(x, k1);
    finalize_kernel<<<1, 64>>>(0, 1.f/(NB*NE*196.f));
    wprep_kernel<<<576, 256>>>(k2, 0);
    conv_kernel<1><<<dim3(49, NB), 256, dsm1>>>();
    finalize_kernel<<<1, 64>>>(1, 1.f/(NB*NE*49.f));
    wprep_kernel<<<576, 256>>>(k3, 1);
    conv_kernel<2><<<dim3(16, NB), 256, dsm2>>>();
    finalize_kernel<<<1, 64>>>(2, 1.f/(NB*NE*16.f));
    wprep_kernel<<<576, 256>>>(k4, 2);
    conv_kernel<3><<<dim3(4, NB), 256, dsm3>>>();
    finalize_kernel<<<1, 64>>>(3, 1.f/(NB*NE*4.f));
    readout_kernel<<<NB, 256>>>(w, out);
}

// round 15
// speedup vs baseline: 2.0565x; 1.2053x over previous
#include <cuda_runtime.h>
#include <cuda_fp16.h>
#include <cstdint>

#define NB 64
#define NE 64
#define NC 64
#define NO 20

// ---------------- device scratch (no allocs allowed) ----------------
__device__ __align__(128) __half g_h1f[(size_t)NB*NE*196*NC];   // conv1 raw relu (fp16, 103MB)
__device__ __align__(128) __half g_h2f[(size_t)NB*NE*49*NC];
__device__ __align__(128) __half g_h3f[(size_t)NB*NE*16*NC];
__device__ float g_feat[NB*NE*NC];
__device__ __align__(128) __half g_kBh[3][NB][9][64][64];  // scale-folded split weights hi [co][ci]
__device__ __align__(128) __half g_kBl[3][NB][9][64][64];  // lo
__device__ float g_C[3][NB][9][64];              // per-tap bias dot products
__device__ float g_sum[4*NC];
__device__ float g_sumsq[4*NC];

__device__ __forceinline__ uint32_t smem_u32(const void* p) {
    return (uint32_t)__cvta_generic_to_shared(p);
}
__device__ __forceinline__ uint32_t ph2(__half a, __half b) {
    unsigned short ua = *(unsigned short*)&a, ub = *(unsigned short*)&b;
    return (uint32_t)ua | ((uint32_t)ub << 16);
}

#define MMA_F16(acc, A0,A1,A2,A3, B0,B1) \
    asm volatile("mma.sync.aligned.m16n8k16.row.col.f32.f16.f16.f32 " \
        "{%0,%1,%2,%3}, {%4,%5,%6,%7}, {%8,%9}, {%0,%1,%2,%3};" \
        : "+f"(acc[0]),"+f"(acc[1]),"+f"(acc[2]),"+f"(acc[3]) \
        : "r"(A0),"r"(A1),"r"(A2),"r"(A3), "r"(B0),"r"(B1))

#define LDMATRIX_X4(r0,r1,r2,r3, addr) \
    asm volatile("ldmatrix.sync.aligned.m8n8.x4.shared.b16 {%0,%1,%2,%3}, [%4];" \
        : "=r"(r0),"=r"(r1),"=r"(r2),"=r"(r3) : "r"(addr))

#define LDS32(r, addr) \
    asm volatile("ld.shared.b32 %0, [%1];" : "=r"(r) : "r"(addr))

#define CP16(dst, src, sz) \
    asm volatile("cp.async.ca.shared.global [%0], [%1], 16, %2;" \
        :: "r"(dst), "l"(src), "r"(sz))
#define CP_COMMIT() asm volatile("cp.async.commit_group;")
#define CP_WAIT1()  asm volatile("cp.async.wait_group 1;")
#define CP_WAIT0()  asm volatile("cp.async.wait_group 0;")

// ---------------- zero stats + feat ----------------
__global__ void zero_kernel() {
    int i = blockIdx.x * 256 + threadIdx.x;
    if (i < 4*NC) { g_sum[i] = 0.f; g_sumsq[i] = 0.f; }
    if (i < NB*NE*NC) g_feat[i] = 0.f;
}

// ---------------- wprep: BN finalize (local) + transpose + scale fold + fp16 split + bias dots ----
__global__ __launch_bounds__(256) void wprep_kernel(const float* __restrict__ kw, int layer,
                                                    float invN) {
    __shared__ float s[64*65];
    __shared__ float s_C[64], s_sc[64], s_bb[64];
    int blk = blockIdx.x;
    int b = blk / 9, kk = blk - b*9;
    int t = threadIdx.x, lane = t & 31;
    if (t < 64) {
        float su = g_sum[layer*64 + t], q = g_sumsq[layer*64 + t];
        float m = su * invN;
        float v = q * invN - m*m;
        float sc = rsqrtf(v + 1e-3f);
        s_sc[t] = sc; s_bb[t] = -m * sc; s_C[t] = 0.f;
    }
    const float* src = kw + ((size_t)b*9 + kk)*4096;
    #pragma unroll
    for (int p = 0; p < 16; p++) {
        int idx = p*256 + t;           // = ci*64 + co
        int ci = idx >> 6, co = idx & 63;
        s[co*65 + ci] = src[idx];
    }
    __syncthreads();
    int ci = t & 63;
    float sc = s_sc[ci];
    float bb = s_bb[ci];
    __half* Dh = &g_kBh[layer][b][kk][0][0];
    __half* Dl = &g_kBl[layer][b][kk][0][0];
    #pragma unroll
    for (int e = 0; e < 16; e++) {
        int idx = e*256 + t;           // = co*64 + ci
        int co = idx >> 6;
        float w = s[co*65 + ci];
        float ws = w * sc;
        __half hi = __float2half(ws);
        __half lo = __float2half(ws - __half2float(hi));
        Dh[idx] = hi; Dl[idx] = lo;
        float c = bb * w;
        #pragma unroll
        for (int o = 16; o; o >>= 1) c += __shfl_down_sync(0xFFFFFFFFu, c, o);
        if (lane == 0) atomicAdd(&s_C[co], c);
    }
    __syncthreads();
    if (t < 64) g_C[layer][b][kk][t] = s_C[t];
}

// ---------------- conv1: Cin=1, 28x28 -> 14x14x64, fp16 output ----------------
__global__ __launch_bounds__(256) void conv1_kernel(const float* __restrict__ x,
                                                    const float* __restrict__ k1) {
    __shared__ float s_in[30*30];
    __shared__ float s_sum[NC];
    __shared__ float s_sq[NC];
    int be = blockIdx.x;
    int t = threadIdx.x;
    for (int i = t; i < 900; i += 256) s_in[i] = 0.f;
    if (t < NC) { s_sum[t] = 0.f; s_sq[t] = 0.f; }
    __syncthreads();
    const float* xp = x + (size_t)be * 784;
    for (int i = t; i < 784; i += 256) {
        int r = i / 28, c = i - r*28;
        s_in[(r+1)*30 + c + 1] = xp[i];
    }
    int cg = t & 15, ig = t >> 4;
    int b = be >> 6;
    float4 w[9];
    const float4* kp = (const float4*)(k1 + (size_t)b * 576);
    #pragma unroll
    for (int j = 0; j < 9; j++) w[j] = kp[j*16 + cg];
    __syncthreads();
    float ls0=0,ls1=0,ls2=0,ls3=0, lq0=0,lq1=0,lq2=0,lq3=0;
    __half* of = g_h1f + (size_t)be * 196 * 64;
    for (int p = ig; p < 196; p += 16) {
        int oy = p / 14, ox = p - oy*14;
        float a0=0,a1=0,a2=0,a3=0;
        #pragma unroll
        for (int ky = 0; ky < 3; ky++)
        #pragma unroll
        for (int kx = 0; kx < 3; kx++) {
            float v = s_in[(2*oy+ky)*30 + 2*ox + kx];
            float4 ww = w[ky*3+kx];
            a0 = fmaf(v, ww.x, a0); a1 = fmaf(v, ww.y, a1);
            a2 = fmaf(v, ww.z, a2); a3 = fmaf(v, ww.w, a3);
        }
        a0 = fmaxf(a0, 0.f); a1 = fmaxf(a1, 0.f);
        a2 = fmaxf(a2, 0.f); a3 = fmaxf(a3, 0.f);
        ls0+=a0; ls1+=a1; ls2+=a2; ls3+=a3;
        lq0+=a0*a0; lq1+=a1*a1; lq2+=a2*a2; lq3+=a3*a3;
        ((uint2*)(of + p*64))[cg] =
            make_uint2(ph2(__float2half(a0), __float2half(a1)),
                       ph2(__float2half(a2), __float2half(a3)));
    }
    int co4 = cg*4;
    atomicAdd(&s_sum[co4+0], ls0); atomicAdd(&s_sum[co4+1], ls1);
    atomicAdd(&s_sum[co4+2], ls2); atomicAdd(&s_sum[co4+3], ls3);
    atomicAdd(&s_sq[co4+0], lq0); atomicAdd(&s_sq[co4+1], lq1);
    atomicAdd(&s_sq[co4+2], lq2); atomicAdd(&s_sq[co4+3], lq3);
    __syncthreads();
    if (t < NC) {
        atomicAdd(&g_sum[t], s_sum[t]);
        atomicAdd(&g_sumsq[t], s_sq[t]);
    }
}

// ---------------- conv layers 2-4: cp.async double-buffered, fp16 2-term mma ----------------
// M-tile 64, 8 warps = 4 m16-tiles x 2 n32-halves. A = fp16 activations (1 plane),
// B = fp16 split weights (hi+lo). D = A*Bh + A*Bl, fp32 accumulate.
template<int LNUM>
__global__ __launch_bounds__(256, 2) void conv_kernel() {
    constexpr int HIN  = (LNUM==1) ? 14 : (LNUM==2) ? 7 : 4;
    constexpr int HOUT = (LNUM==1) ? 7  : (LNUM==2) ? 4 : 2;
    constexpr bool LAST = (LNUM==3);
    constexpr int POS   = HOUT*HOUT;
    constexpr int MTASK = NE*POS;
    constexpr int RS    = 144;
    constexpr int A_O = 0, B_HI = 64*RS, B_LO = 128*RS;
    constexpr int STAGE = 192*RS;        // 27648
    constexpr int BIAS_O = 2*STAGE;

    __shared__ float s_sum[64], s_sq[64];
    __shared__ int s_ri[64];
    extern __shared__ char dsm[];
    float* s_bias = (float*)(dsm + BIAS_O);

    int b = blockIdx.y, m0 = blockIdx.x*64, t = threadIdx.x;
    int wid = t >> 5, lane = t & 31;

    if (t < 64) {
        s_sum[t] = 0.f; s_sq[t] = 0.f;
        int gic = m0 + t;
        int e = gic / POS, p = gic - e*POS;
        s_ri[t] = (e << 16) | ((p / HOUT) << 8) | (p % HOUT);
    }
    {
        const float* Cb = &g_C[LNUM-1][b][0][0];
        for (int idx = t; idx < POS*64; idx += 256) {
            int p = idx >> 6, co = idx & 63;
            int oy = p / HOUT, ox = p - oy*HOUT;
            float s = 0.f;
            #pragma unroll
            for (int ky = 0; ky < 3; ky++) {
                int iy = 2*oy - 1 + ky;
                if ((unsigned)iy >= (unsigned)HIN) continue;
                #pragma unroll
                for (int kx = 0; kx < 3; kx++) {
                    int ix = 2*ox - 1 + kx;
                    if ((unsigned)ix < (unsigned)HIN) s += Cb[(ky*3+kx)*64 + co];
                }
            }
            s_bias[idx] = s;
        }
    }
    __syncthreads();

    const __half* pa = ((LNUM==1) ? g_h1f : (LNUM==2) ? g_h2f : g_h3f)
                     + (size_t)b*NE*HIN*HIN*64;
    __half* of = (LNUM==1) ? g_h2f : g_h3f;
    const char* pac = (const char*)pa;
    const char* Bhc = (const char*)&g_kBh[LNUM-1][b][0][0][0];
    const char* Blc = (const char*)&g_kBl[LNUM-1][b][0][0][0];

    // loader precompute: rows r0 = t>>3 and r0+32, seg = t&7 (16B each); rows are 128B.
    int seg = t & 7, r0 = t >> 3, r1 = r0 + 32;
    int inf0 = s_ri[r0], inf1 = s_ri[r1];
    int e0 = inf0 >> 16, iyb0 = 2*((inf0 >> 8) & 255) - 1, ixb0 = 2*(inf0 & 255) - 1;
    int e1 = inf1 >> 16, iyb1 = 2*((inf1 >> 8) & 255) - 1, ixb1 = 2*(inf1 & 255) - 1;
    int ab0 = e0*HIN*HIN*128 + seg*16;
    int ab1 = e1*HIN*HIN*128 + seg*16;
    uint32_t dA0 = A_O + r0*RS + seg*16, dA1 = A_O + r1*RS + seg*16;
    uint32_t dB0 = B_HI + r0*RS + seg*16, dB1 = B_HI + r1*RS + seg*16;
    int rbB0 = r0*128 + seg*16, rbB1 = r1*128 + seg*16;

    uint32_t smem0 = smem_u32(dsm);

    auto issue = [&](int kk, uint32_t sb) {
        int ky = kk/3, kx = kk - (kk/3)*3;
        int iy0 = iyb0 + ky, ix0 = ixb0 + kx;
        int iy1 = iyb1 + ky, ix1 = ixb1 + kx;
        bool v0 = (unsigned)iy0 < (unsigned)HIN && (unsigned)ix0 < (unsigned)HIN;
        bool v1 = (unsigned)iy1 < (unsigned)HIN && (unsigned)ix1 < (unsigned)HIN;
        int o0 = v0 ? (ab0 + (iy0*HIN + ix0)*128) : 0;
        int o1 = v1 ? (ab1 + (iy1*HIN + ix1)*128) : 0;
        int s0 = v0 ? 16 : 0, s1 = v1 ? 16 : 0;
        CP16(sb + dA0, pac + o0, s0);
        CP16(sb + dA1, pac + o1, s1);
        int bo = kk*8192;
        CP16(sb + dB0,                 Bhc + bo + rbB0, 16);
        CP16(sb + dB1,                 Bhc + bo + rbB1, 16);
        CP16(sb + dB0 + (B_LO - B_HI), Blc + bo + rbB0, 16);
        CP16(sb + dB1 + (B_LO - B_HI), Blc + bo + rbB1, 16);
    };

    int mw = wid & 3, ntb = (wid >> 2) * 4;
    float acc[4][4];
    #pragma unroll
    for (int nt = 0; nt < 4; nt++)
        #pragma unroll
        for (int j = 0; j < 4; j++) acc[nt][j] = 0.f;

    auto domma = [&](uint32_t sb) {
        uint32_t a_base = sb + A_O + mw*(16*RS) + (lane & 15)*RS + ((lane >> 4) * 16);
        uint32_t b_base = sb + B_HI + (ntb*8 + (lane >> 2))*RS + (lane & 3)*4;
        #pragma unroll
        for (int ks = 0; ks < 4; ks++) {
            uint32_t a0,a1,a2,a3;
            LDMATRIX_X4(a0,a1,a2,a3, a_base + ks*32);
            #pragma unroll
            for (int nt = 0; nt < 4; nt++) {
                uint32_t ba = b_base + nt*(8*RS) + ks*32;
                uint32_t bh0,bh1,bl0,bl1;
                LDS32(bh0, ba);
                LDS32(bh1, ba + 16);
                LDS32(bl0, ba + (B_LO - B_HI));
                LDS32(bl1, ba + (B_LO - B_HI) + 16);
                MMA_F16(acc[nt], a0,a1,a2,a3, bh0,bh1);
                MMA_F16(acc[nt], a0,a1,a2,a3, bl0,bl1);
            }
        }
    };

    // ---- 2-stage pipeline over 9 chunks ----
    issue(0, smem0);
    CP_COMMIT();
    #pragma unroll
    for (int kk = 0; kk < 9; kk++) {
        if (kk < 8) {
            issue(kk+1, smem0 + ((kk+1) & 1)*STAGE);
            CP_COMMIT();
            CP_WAIT1();
        } else {
            CP_WAIT0();
        }
        __syncthreads();
        domma(smem0 + (kk & 1)*STAGE);
        __syncthreads();
    }

    // ---- epilogue: +bias, relu, stats, fp16 store / max-pool ----
    int q = lane & 3, r = lane >> 2;
    int g0 = m0 + mw*16 + r, g1 = g0 + 8;
    int E0 = g0 / POS, p0 = g0 - E0*POS;
    int E1 = g1 / POS, p1 = g1 - E1*POS;
    float lsum[8], lsq[8];
    #pragma unroll
    for (int nt = 0; nt < 4; nt++) {
        int col = (ntb + nt)*8 + q*2;
        float d0 = fmaxf(acc[nt][0] + s_bias[p0*64+col],   0.f);
        float d1 = fmaxf(acc[nt][1] + s_bias[p0*64+col+1], 0.f);
        float d2 = fmaxf(acc[nt][2] + s_bias[p1*64+col],   0.f);
        float d3 = fmaxf(acc[nt][3] + s_bias[p1*64+col+1], 0.f);
        lsum[2*nt]   = d0 + d2;  lsq[2*nt]   = d0*d0 + d2*d2;
        lsum[2*nt+1] = d1 + d3;  lsq[2*nt+1] = d1*d1 + d3*d3;
        if (!LAST) {
            *(uint32_t*)(of + ((size_t)b*MTASK + g0)*64 + col) =
                ph2(__float2half(d0), __float2half(d1));
            *(uint32_t*)(of + ((size_t)b*MTASK + g1)*64 + col) =
                ph2(__float2half(d2), __float2half(d3));
        } else {
            int* fp0 = (int*)(g_feat + (size_t)(b*NE + E0)*64 + col);
            atomicMax(&fp0[0], __float_as_int(d0));
            atomicMax(&fp0[1], __float_as_int(d1));
            int* fp1 = (int*)(g_feat + (size_t)(b*NE + E1)*64 + col);
            atomicMax(&fp1[0], __float_as_int(d2));
            atomicMax(&fp1[1], __float_as_int(d3));
        }
    }
    #pragma unroll
    for (int j = 0; j < 8; j++) {
        #pragma unroll
        for (int o = 4; o <= 16; o <<= 1) {
            lsum[j] += __shfl_xor_sync(0xFFFFFFFFu, lsum[j], o);
            lsq[j]  += __shfl_xor_sync(0xFFFFFFFFu, lsq[j],  o);
        }
    }
    if (lane < 4) {
        #pragma unroll
        for (int nt = 0; nt < 4; nt++) {
            int col = (ntb + nt)*8 + lane*2;
            atomicAdd(&s_sum[col],   lsum[2*nt]);
            atomicAdd(&s_sum[col+1], lsum[2*nt+1]);
            atomicAdd(&s_sq[col],    lsq[2*nt]);
            atomicAdd(&s_sq[col+1],  lsq[2*nt+1]);
        }
    }
    __syncthreads();
    if (t < 64) {
        atomicAdd(&g_sum[LNUM*NC + t],   s_sum[t]);
        atomicAdd(&g_sumsq[LNUM*NC + t], s_sq[t]);
    }
}

// ---------------- readout: local BN finalize, normalize pooled feats, per-task matmul ----
__global__ __launch_bounds__(256) void readout_kernel(const float* __restrict__ w_ro,
                                                      float* __restrict__ out, float invN) {
    __shared__ float s_w[64*20];
    __shared__ float s_f[64*64];
    __shared__ float s_sc[64], s_bi[64];
    int b = blockIdx.x, t = threadIdx.x;
    if (t < 64) {
        float su = g_sum[192 + t], q = g_sumsq[192 + t];
        float m = su * invN;
        float v = q * invN - m*m;
        float sc = rsqrtf(v + 1e-3f);
        s_sc[t] = sc; s_bi[t] = -m * sc;
    }
    for (int i = t; i < 1280; i += 256) s_w[i] = w_ro[(size_t)b*1280 + i];
    __syncthreads();
    const float* fp = g_feat + (size_t)b*4096;
    for (int i = t; i < 4096; i += 256) {
        int c = i & 63;
        s_f[i] = fmaf(fp[i], s_sc[c], s_bi[c]);
    }
    __syncthreads();
    for (int idx = t; idx < 1280; idx += 256) {
        int e = idx/20, o = idx - e*20;
        float s = 0.f;
        const float* fe = s_f + e*64;
        #pragma unroll 16
        for (int c = 0; c < 64; c++) s = fmaf(fe[c], s_w[c*20+o], s);
        out[(size_t)b*1280 + idx] = s;
    }
}

// ---------------- launch ----------------
extern "C" void kernel_launch(void* const* d_in, const int* in_sizes, int n_in,
                              void* d_out, int out_size) {
    const float* x  = (const float*)d_in[0];
    const float* k1 = (const float*)d_in[1];
    const float* k2 = (const float*)d_in[2];
    const float* k3 = (const float*)d_in[3];
    const float* k4 = (const float*)d_in[4];
    const float* w  = (const float*)d_in[5];
    float* out = (float*)d_out;
    (void)in_sizes; (void)n_in; (void)out_size;

    const int STAGE2 = 2*192*144;                  // 55296
    const int dsm1 = STAGE2 + 49*64*4;             // 67840
    const int dsm2 = STAGE2 + 16*64*4;             // 59392
    const int dsm3 = STAGE2 + 4*64*4;              // 56320
    cudaFuncSetAttribute(conv_kernel<1>, cudaFuncAttributeMaxDynamicSharedMemorySize, dsm1);
    cudaFuncSetAttribute(conv_kernel<2>, cudaFuncAttributeMaxDynamicSharedMemorySize, dsm2);
    cudaFuncSetAttribute(conv_kernel<3>, cudaFuncAttributeMaxDynamicSharedMemorySize, dsm3);

    zero_kernel<<<1024, 256>>>();
    conv1_kernel<<<NB*NE, 256>>>(x, k1);
    wprep_kernel<<<576, 256>>>(k2, 0, 1.f/(NB*NE*196.f));
    conv_kernel<1><<<dim3(49, NB), 256, dsm1>>>();
    wprep_kernel<<<576, 256>>>(k3, 1, 1.f/(NB*NE*49.f));
    conv_kernel<2><<<dim3(16, NB), 256, dsm2>>>();
    wprep_kernel<<<576, 256>>>(k4, 2, 1.f/(NB*NE*16.f));
    conv_kernel<3><<<dim3(4, NB), 256, dsm3>>>();
    readout_kernel<<<NB, 256>>>(w, out, 1.f/(NB*NE*4.f));
}